// round 6
// baseline (speedup 1.0000x reference)
#include <cuda_runtime.h>
#include <cuda_bf16.h>
#include <cstdint>

#define COULOMB_K 14.3996454784936f
#define BLOCK     256
#define EDGE_GRID (148 * 8)   // persistent-ish grid, ~13 iters/thread

// ---------------- prologue: zero output (vectorized) ----------------
__global__ void zero_kernel(float4* __restrict__ out4, int n4) {
    int i = blockIdx.x * blockDim.x + threadIdx.x;
    if (i < n4) out4[i] = make_float4(0.f, 0.f, 0.f, 0.f);
}
__global__ void zero_tail_kernel(float* __restrict__ out, int start, int n) {
    int i = start + threadIdx.x;
    if (i < n) out[i] = 0.0f;
}

// message for one edge: erf(r/(sqrt2*gamma)) * fcut(r) / r   (charge,K folded out)
__device__ __forceinline__ float edge_msg(float r, float ss, float sd) {
    float g2  = 2.0f * fmaf(ss, ss, sd * sd);    // 2*(ss^2+sd^2)
    float arg = r * rsqrtf(g2);                  // r / (sqrt2 * gamma)
    float x = r * 0.2f;                          // r / CUTOFF
    float p = fmaf(-6.0f, x, 15.0f);
    p = fmaf(p, x, -10.0f);
    float fcut = fmaf(x * x * x, p, 1.0f);       // 1 -10x^3 +15x^4 -6x^5
    fcut = (r <= 5.0f) ? fcut : 0.0f;
    return erff(arg) * fcut * __fdividef(1.0f, r);
}

// 4 edges/thread, grid-stride, next iteration's streams prefetched
__global__ void __launch_bounds__(BLOCK, 6)
edge_kernel(const float* __restrict__ bond,
            const int*   __restrict__ src,
            const int*   __restrict__ dst,
            const float* __restrict__ sigma,
            float*       __restrict__ out,
            int n4) {
    const float4* bond4 = reinterpret_cast<const float4*>(bond);
    const int4*   src4  = reinterpret_cast<const int4*>(src);
    const int4*   dst4  = reinterpret_cast<const int4*>(dst);

    int stride = gridDim.x * BLOCK;
    int t = blockIdx.x * BLOCK + threadIdx.x;
    if (t >= n4) return;

    // preload first group's streams
    float4 r = __ldcs(bond4 + t);
    int4   s = __ldcs(src4 + t);
    int4   d = __ldcs(dst4 + t);

    for (;;) {
        int tn = t + stride;
        bool more = tn < n4;

        // prefetch next group's streams before touching current data
        float4 rn; int4 sn, dn;
        if (more) {
            rn = __ldcs(bond4 + tn);
            sn = __ldcs(src4 + tn);
            dn = __ldcs(dst4 + tn);
        }

        // 8 scattered gathers, issued contiguously
        float ss0 = __ldg(sigma + s.x);
        float ss1 = __ldg(sigma + s.y);
        float ss2 = __ldg(sigma + s.z);
        float ss3 = __ldg(sigma + s.w);
        float sd0 = __ldg(sigma + d.x);
        float sd1 = __ldg(sigma + d.y);
        float sd2 = __ldg(sigma + d.z);
        float sd3 = __ldg(sigma + d.w);

        atomicAdd(out + d.x, edge_msg(r.x, ss0, sd0));
        atomicAdd(out + d.y, edge_msg(r.y, ss1, sd1));
        atomicAdd(out + d.z, edge_msg(r.z, ss2, sd2));
        atomicAdd(out + d.w, edge_msg(r.w, ss3, sd3));

        if (!more) break;
        r = rn; s = sn; d = dn; t = tn;
    }
}

__global__ void edge_tail_kernel(const float* __restrict__ bond,
                                 const int*   __restrict__ src,
                                 const int*   __restrict__ dst,
                                 const float* __restrict__ sigma,
                                 float*       __restrict__ out,
                                 int start, int n_edges) {
    int e = start + blockIdx.x * blockDim.x + threadIdx.x;
    if (e < n_edges) {
        float ss = __ldg(sigma + src[e]);
        float sd = __ldg(sigma + dst[e]);
        atomicAdd(out + dst[e], edge_msg(bond[e], ss, sd));
    }
}

// ---------------- epilogue: out[i] *= K * charge[i]  (vectorized) ----------------
__global__ void scale_kernel(const float4* __restrict__ charge4,
                             float4* __restrict__ out4, int n4) {
    int i = blockIdx.x * blockDim.x + threadIdx.x;
    if (i < n4) {
        float4 c = __ldg(charge4 + i);
        float4 o = out4[i];
        o.x *= COULOMB_K * c.x;
        o.y *= COULOMB_K * c.y;
        o.z *= COULOMB_K * c.z;
        o.w *= COULOMB_K * c.w;
        out4[i] = o;
    }
}
__global__ void scale_tail_kernel(const float* __restrict__ charge,
                                  float* __restrict__ out, int start, int n) {
    int i = start + threadIdx.x;
    if (i < n) out[i] *= COULOMB_K * charge[i];
}

extern "C" void kernel_launch(void* const* d_in, const int* in_sizes, int n_in,
                              void* d_out, int out_size) {
    const float* charge    = (const float*)d_in[0];
    const float* sigma     = (const float*)d_in[1];
    const float* bond_dist = (const float*)d_in[2];
    const int*   src       = (const int*)d_in[3];
    const int*   dst       = (const int*)d_in[4];
    float* out = (float*)d_out;

    int n_nodes = in_sizes[0];
    int n_edges = in_sizes[2];

    // zero output
    int nz4 = n_nodes / 4;
    zero_kernel<<<(nz4 + BLOCK - 1) / BLOCK, BLOCK>>>(
        reinterpret_cast<float4*>(out), nz4);
    if (nz4 * 4 < n_nodes)
        zero_tail_kernel<<<1, 256>>>(out, nz4 * 4, n_nodes);

    // edge accumulation
    int n4 = n_edges / 4;
    if (n4 > 0) {
        int grid = (n4 + BLOCK - 1) / BLOCK;
        if (grid > EDGE_GRID) grid = EDGE_GRID;
        edge_kernel<<<grid, BLOCK>>>(bond_dist, src, dst, sigma, out, n4);
    }
    if (n4 * 4 < n_edges) {
        int tail = n_edges - n4 * 4;
        edge_tail_kernel<<<(tail + BLOCK - 1) / BLOCK, BLOCK>>>(
            bond_dist, src, dst, sigma, out, n4 * 4, n_edges);
    }

    // scale by K * charge
    scale_kernel<<<(nz4 + BLOCK - 1) / BLOCK, BLOCK>>>(
        reinterpret_cast<const float4*>(charge),
        reinterpret_cast<float4*>(out), nz4);
    if (nz4 * 4 < n_nodes)
        scale_tail_kernel<<<1, 256>>>(charge, out, nz4 * 4, n_nodes);
}